// round 3
// baseline (speedup 1.0000x reference)
#include <cuda_runtime.h>
#include <math.h>

#define G_N   40000
#define P_N   5
#define ZD    32
#define FD    64
#define HD    32
#define UVN   256
#define UV2   (UVN*UVN)
#define CC    64

// -------- scratch (device globals: no allocation allowed) --------
__device__ float g_uvmap[HD * UV2];          // 8 MB   CNN input
__device__ float g_buf0[CC * UV2];           // 16 MB
__device__ float g_buf1[CC * UV2];           // 16 MB
__device__ float g_bias1[P_N * 128];
__device__ float g_bias2[P_N * 128];
__device__ int   g_cnt[P_N];
__device__ int   g_cursor[P_N];
__device__ int   g_poff[P_N + 1];
__device__ int   g_order[40960];
__device__ float g_stats[2 * CC];            // mean[64], invstd[64]

__device__ __forceinline__ float lrelu(float x) { return x > 0.f ? x : 0.01f * x; }

// ============================================================
// prep kernels
// ============================================================
__global__ void clear_uvmap_kernel() {
    int i = blockIdx.x * blockDim.x + threadIdx.x;
    float4 z = make_float4(0.f, 0.f, 0.f, 0.f);
    if (i < HD * UV2 / 4) reinterpret_cast<float4*>(g_uvmap)[i] = z;
}

// per-part folded bias: bias = b_in + latent_f[p] . W_in[0:64]
__global__ void partbias_kernel(const float* __restrict__ latent_f,
                                const float* __restrict__ w1in, const float* __restrict__ b1in,
                                const float* __restrict__ w2in, const float* __restrict__ b2in) {
    int p = blockIdx.x, n = threadIdx.x;
    float s1 = b1in[p * 128 + n];
    float s2 = b2in[p * 128 + n];
    for (int k = 0; k < FD; k++) {
        float f = latent_f[p * FD + k];
        s1 += f * w1in[(p * 96 + k) * 128 + n];
        s2 += f * w2in[(p * 110 + k) * 128 + n];
    }
    g_bias1[p * 128 + n] = s1;
    g_bias2[p * 128 + n] = s2;
    if (p == 0 && n < P_N) g_cnt[n] = 0;
}

__global__ void count_kernel(const int* __restrict__ gs_part) {
    int g = blockIdx.x * blockDim.x + threadIdx.x;
    if (g < G_N) atomicAdd(&g_cnt[gs_part[g]], 1);
}

__global__ void offsets_kernel() {
    if (threadIdx.x == 0) {
        int off = 0;
        for (int p = 0; p < P_N; p++) {
            g_poff[p] = off;
            off += ((g_cnt[p] + 63) >> 6) << 6;   // pad each part to 64
            g_cursor[p] = 0;
        }
        g_poff[P_N] = off;
    }
}

__global__ void scatter_kernel(const int* __restrict__ gs_part) {
    int g = blockIdx.x * blockDim.x + threadIdx.x;
    if (g < G_N) {
        int p = gs_part[g];
        int pos = g_poff[p] + atomicAdd(&g_cursor[p], 1);
        g_order[pos] = g;
    }
}

// ============================================================
// fused per-part MLP1 + MLP2 (64 gaussians / block, 256 threads)
// ============================================================
// GEMM: C[64x128] = act(As[Kx64] * Wg[Kx128] + bias), As k-major in smem.
__device__ __forceinline__ void layer128(const float* As, const float* __restrict__ Wg,
                                         const float* __restrict__ bias,
                                         float* Ws, float* Os, int K, bool act, int tid) {
    const int g0 = (tid & 15) * 4;
    const int n0 = (tid >> 4) * 8;
    float c[4][8];
#pragma unroll
    for (int j = 0; j < 8; j++) {
        float b = bias[n0 + j];
#pragma unroll
        for (int i = 0; i < 4; i++) c[i][j] = b;
    }
    for (int kt = 0; kt < K; kt += 32) {
        int kk = min(32, K - kt);
        for (int idx = tid; idx < kk * 128; idx += 256) Ws[idx] = Wg[kt * 128 + idx];
        __syncthreads();
#pragma unroll 4
        for (int k = 0; k < kk; k++) {
            float4 a  = *reinterpret_cast<const float4*>(As + (kt + k) * 64 + g0);
            float4 w0 = *reinterpret_cast<const float4*>(Ws + k * 128 + n0);
            float4 w1 = *reinterpret_cast<const float4*>(Ws + k * 128 + n0 + 4);
            float av[4] = {a.x, a.y, a.z, a.w};
            float wv[8] = {w0.x, w0.y, w0.z, w0.w, w1.x, w1.y, w1.z, w1.w};
#pragma unroll
            for (int i = 0; i < 4; i++)
#pragma unroll
                for (int j = 0; j < 8; j++) c[i][j] += av[i] * wv[j];
        }
        __syncthreads();
    }
#pragma unroll
    for (int j = 0; j < 8; j++) {
        float4 v;
        v.x = act ? lrelu(c[0][j]) : c[0][j];
        v.y = act ? lrelu(c[1][j]) : c[1][j];
        v.z = act ? lrelu(c[2][j]) : c[2][j];
        v.w = act ? lrelu(c[3][j]) : c[3][j];
        *reinterpret_cast<float4*>(Os + (n0 + j) * 64 + g0) = v;
    }
}

__global__ void __launch_bounds__(256) mlp_kernel(
    const float* __restrict__ latent_z, const float* __restrict__ cano_xyz,
    const float* __restrict__ w1in,
    const float* __restrict__ w1hid, const float* __restrict__ b1hid,
    const float* __restrict__ w1out, const float* __restrict__ b1out,
    const float* __restrict__ w2in,
    const float* __restrict__ w2hid, const float* __restrict__ b2hid,
    const float* __restrict__ w2out, const float* __restrict__ b2out,
    const int* __restrict__ uv_idx) {
    extern __shared__ float sm[];
    float* Es = sm;                     // [48][64]  rows: 0-31 z, 32-34 xyz, 35-45 attrs
    float* Ha = Es + 48 * 64;           // [128][64]
    float* Hb = Ha + 128 * 64;          // [128][64]
    float* Ws = Hb + 128 * 64;          // 4096 floats staging
    int*   gidxs = reinterpret_cast<int*>(Ws + 4096); // [64]
    int*   uvs   = gidxs + 64;                         // [64]

    const int tid = threadIdx.x;
    const int base = blockIdx.x * 64;
    if (base >= g_poff[P_N]) return;
    int p = 0;
    while (p < P_N - 1 && base >= g_poff[p + 1]) p++;
    const int seg0 = g_poff[p];
    const int cnt  = g_cnt[p];

    if (tid < 64) {
        int srow = base - seg0 + tid;
        int gi = (srow < cnt) ? g_order[base + tid] : -1;
        gidxs[tid] = gi;
        uvs[tid] = (gi >= 0) ? uv_idx[gi] : 0;
    }
    __syncthreads();

    // stage z + xyz (k-major)
    for (int idx = tid; idx < 64 * ZD; idx += 256) {
        int g = idx >> 5, k = idx & 31;
        int gi = gidxs[g];
        Es[k * 64 + g] = (gi >= 0) ? latent_z[gi * ZD + k] : 0.f;
    }
    for (int idx = tid; idx < 64 * 3; idx += 256) {
        int g = idx / 3, k = idx - g * 3;
        int gi = gidxs[g];
        Es[(32 + k) * 64 + g] = (gi >= 0) ? cano_xyz[gi * 3 + k] : 0.f;
    }
    __syncthreads();

    // ---- MLP1 ----
    layer128(Es, w1in + (p * 96 + 64) * 128, g_bias1 + p * 128, Ws, Ha, 32, true, tid);
    layer128(Ha, w1hid + p * 2 * 16384,          b1hid + p * 2 * 128,       Ws, Hb, 128, true, tid);
    layer128(Hb, w1hid + p * 2 * 16384 + 16384,  b1hid + p * 2 * 128 + 128, Ws, Ha, 128, true, tid);

    // attrs = Ha . W1out + b  (N=11), stored into Es rows 35..45
    for (int idx = tid; idx < 128 * 11; idx += 256) Ws[idx] = w1out[p * 128 * 11 + idx];
    __syncthreads();
    {
        int g = tid & 63, nb = tid >> 6;   // nb 0..3
        float s0 = 0.f, s1 = 0.f, s2 = 0.f;
        bool has2 = (nb + 8) < 11;
        for (int k = 0; k < 128; k++) {
            float a = Ha[k * 64 + g];
            s0 += a * Ws[k * 11 + nb];
            s1 += a * Ws[k * 11 + nb + 4];
            if (has2) s2 += a * Ws[k * 11 + nb + 8];
        }
        Es[(35 + nb) * 64 + g]     = s0 + b1out[p * 11 + nb];
        Es[(35 + nb + 4) * 64 + g] = s1 + b1out[p * 11 + nb + 4];
        if (has2) Es[(35 + nb + 8) * 64 + g] = s2 + b1out[p * 11 + nb + 8];
    }
    __syncthreads();

    // ---- MLP2 ----  (x2 tail = rows 64..109 of W2in -> Es rows 0..45)
    layer128(Es, w2in + (p * 110 + 64) * 128, g_bias2 + p * 128, Ws, Hb, 46, true, tid);
    layer128(Hb, w2hid + p * 2 * 16384,          b2hid + p * 2 * 128,       Ws, Ha, 128, true, tid);
    layer128(Ha, w2hid + p * 2 * 16384 + 16384,  b2hid + p * 2 * 128 + 128, Ws, Hb, 128, true, tid);

    // final N=32 + scatter to uvmap
    for (int idx = tid; idx < 128 * 32; idx += 256) Ws[idx] = w2out[p * 128 * 32 + idx];
    __syncthreads();
    {
        const int g0 = (tid & 15) * 4;
        const int n0 = (tid >> 4) * 2;
        float c[4][2];
#pragma unroll
        for (int j = 0; j < 2; j++) {
            float b = b2out[p * 32 + n0 + j];
#pragma unroll
            for (int i = 0; i < 4; i++) c[i][j] = b;
        }
#pragma unroll 4
        for (int k = 0; k < 128; k++) {
            float4 a = *reinterpret_cast<const float4*>(Hb + k * 64 + g0);
            float w0 = Ws[k * 32 + n0], w1 = Ws[k * 32 + n0 + 1];
            float av[4] = {a.x, a.y, a.z, a.w};
#pragma unroll
            for (int i = 0; i < 4; i++) { c[i][0] += av[i] * w0; c[i][1] += av[i] * w1; }
        }
#pragma unroll
        for (int i = 0; i < 4; i++) {
            int gi = gidxs[g0 + i];
            if (gi >= 0) {
                int uv = uvs[g0 + i];
                g_uvmap[(n0 + 0) * UV2 + uv] = c[i][0];
                g_uvmap[(n0 + 1) * UV2 + uv] = c[i][1];
            }
        }
    }
}

// ============================================================
// CNN
// ============================================================
// 3x3 SAME conv. pre: 0 = none, 1 = relu, 2 = instnorm+relu, 3 = instnorm.
// Block: 16x16 pixels, 32 couts. Thread: 2x2 pixels x 8 couts.
__global__ void __launch_bounds__(256) conv3x3_kernel(
    const float* __restrict__ in, int cin,
    const float* __restrict__ w, const float* __restrict__ bias,
    float* __restrict__ out, int pre) {
    __shared__ float ins[16][18][20];
    __shared__ float wsf[32 * 144];     // [co][ci*9+tap] per 16-cin chunk

    const int tid = threadIdx.x;
    const int bx = blockIdx.x, by = blockIdx.y, cob = blockIdx.z * 32;
    const int qx = tid & 7, qy = (tid >> 3) & 7, qc = tid >> 6;
    const int x0 = 2 * qx, y0 = 2 * qy;

    float acc[2][2][8];
#pragma unroll
    for (int a = 0; a < 2; a++)
#pragma unroll
        for (int b = 0; b < 2; b++)
#pragma unroll
            for (int j = 0; j < 8; j++) acc[a][b][j] = 0.f;

    for (int cc = 0; cc < cin; cc += 16) {
        for (int idx = tid; idx < 16 * 18 * 18; idx += 256) {
            int ci = idx / 324;
            int rr = idx - ci * 324;
            int r = rr / 18, c = rr - r * 18;
            int gy = by * 16 + r - 1, gx = bx * 16 + c - 1;
            float v = 0.f;
            if ((unsigned)gy < 256u && (unsigned)gx < 256u) {
                v = in[(cc + ci) * UV2 + gy * 256 + gx];
                if (pre >= 2) v = (v - g_stats[cc + ci]) * g_stats[64 + cc + ci];
                if (pre == 1 || pre == 2) v = fmaxf(v, 0.f);
            }
            ins[ci][r][c] = v;
        }
        for (int idx = tid; idx < 32 * 144; idx += 256) {
            int co = idx / 144, r = idx - co * 144;
            wsf[idx] = w[(cob + co) * cin * 9 + cc * 9 + r];
        }
        __syncthreads();

        for (int ci = 0; ci < 16; ci++) {
#pragma unroll
            for (int tap = 0; tap < 9; tap++) {
                const int ky = tap / 3, kx = tap - ky * 3;
                float wv[8];
#pragma unroll
                for (int j = 0; j < 8; j++) wv[j] = wsf[(qc * 8 + j) * 144 + ci * 9 + tap];
                float v00 = ins[ci][y0 + ky][x0 + kx];
                float v01 = ins[ci][y0 + ky][x0 + kx + 1];
                float v10 = ins[ci][y0 + 1 + ky][x0 + kx];
                float v11 = ins[ci][y0 + 1 + ky][x0 + kx + 1];
#pragma unroll
                for (int j = 0; j < 8; j++) {
                    acc[0][0][j] += v00 * wv[j];
                    acc[0][1][j] += v01 * wv[j];
                    acc[1][0][j] += v10 * wv[j];
                    acc[1][1][j] += v11 * wv[j];
                }
            }
        }
        __syncthreads();
    }
#pragma unroll
    for (int iy = 0; iy < 2; iy++)
#pragma unroll
        for (int ix = 0; ix < 2; ix++) {
            int yy = by * 16 + y0 + iy, xx = bx * 16 + x0 + ix;
#pragma unroll
            for (int j = 0; j < 8; j++) {
                int co = cob + qc * 8 + j;
                out[co * UV2 + yy * 256 + xx] = acc[iy][ix][j] + bias[co];
            }
        }
}

// conv_out: 64 -> 3, input instance-normalized (no relu), sigmoid output.
__global__ void __launch_bounds__(256) convout_kernel(
    const float* __restrict__ in,
    const float* __restrict__ w, const float* __restrict__ bias,
    float* __restrict__ out) {
    __shared__ float ins[16][18][20];
    __shared__ float wsf[3 * 144];

    const int tid = threadIdx.x;
    const int bx = blockIdx.x, by = blockIdx.y;
    const int x = tid & 15, y = tid >> 4;

    float acc[3] = {0.f, 0.f, 0.f};
    for (int cc = 0; cc < CC; cc += 16) {
        for (int idx = tid; idx < 16 * 18 * 18; idx += 256) {
            int ci = idx / 324;
            int rr = idx - ci * 324;
            int r = rr / 18, c = rr - r * 18;
            int gy = by * 16 + r - 1, gx = bx * 16 + c - 1;
            float v = 0.f;
            if ((unsigned)gy < 256u && (unsigned)gx < 256u) {
                v = in[(cc + ci) * UV2 + gy * 256 + gx];
                v = (v - g_stats[cc + ci]) * g_stats[64 + cc + ci];
            }
            ins[ci][r][c] = v;
        }
        for (int idx = tid; idx < 3 * 144; idx += 256) {
            int co = idx / 144, r = idx - co * 144;
            wsf[idx] = w[co * CC * 9 + cc * 9 + r];
        }
        __syncthreads();
        for (int ci = 0; ci < 16; ci++) {
#pragma unroll
            for (int tap = 0; tap < 9; tap++) {
                const int ky = tap / 3, kx = tap - ky * 3;
                float v = ins[ci][y + ky][x + kx];
#pragma unroll
                for (int co = 0; co < 3; co++) acc[co] += v * wsf[co * 144 + ci * 9 + tap];
            }
        }
        __syncthreads();
    }
#pragma unroll
    for (int co = 0; co < 3; co++) {
        float v = acc[co] + bias[co];
        out[co * UV2 + (by * 16 + y) * 256 + bx * 16 + x] = 1.f / (1.f + expf(-v));
    }
}

// per-channel instance-norm stats over 256x256
__global__ void in_stats_kernel(const float* __restrict__ x) {
    const int c = blockIdx.x;
    const float* p = x + c * UV2;
    float s = 0.f, q = 0.f;
    for (int i = threadIdx.x; i < UV2; i += 256) {
        float v = p[i];
        s += v; q += v * v;
    }
    __shared__ float rs[256], rq[256];
    rs[threadIdx.x] = s; rq[threadIdx.x] = q;
    __syncthreads();
    for (int o = 128; o > 0; o >>= 1) {
        if (threadIdx.x < o) { rs[threadIdx.x] += rs[threadIdx.x + o]; rq[threadIdx.x] += rq[threadIdx.x + o]; }
        __syncthreads();
    }
    if (threadIdx.x == 0) {
        float m = rs[0] * (1.f / UV2);
        float var = rq[0] * (1.f / UV2) - m * m;
        g_stats[c] = m;
        g_stats[64 + c] = rsqrtf(fmaxf(var, 0.f) + 1e-5f);
    }
}

// ============================================================
// host launch
// ============================================================
#define MLP_SMEM ((48 * 64 + 128 * 64 * 2 + 4096) * 4 + 128 * 4)

extern "C" void kernel_launch(void* const* d_in, const int* in_sizes, int n_in,
                              void* d_out, int out_size) {
    const float* latent_z = (const float*)d_in[0];
    const float* latent_f = (const float*)d_in[1];
    const float* cano_xyz = (const float*)d_in[2];
    const float* w1in  = (const float*)d_in[3];
    const float* b1in  = (const float*)d_in[4];
    const float* w1hid = (const float*)d_in[5];
    const float* b1hid = (const float*)d_in[6];
    const float* w1out = (const float*)d_in[7];
    const float* b1out = (const float*)d_in[8];
    const float* w2in  = (const float*)d_in[9];
    const float* b2in  = (const float*)d_in[10];
    const float* w2hid = (const float*)d_in[11];
    const float* b2hid = (const float*)d_in[12];
    const float* w2out = (const float*)d_in[13];
    const float* b2out = (const float*)d_in[14];
    const float* cinw  = (const float*)d_in[15];
    const float* cinb  = (const float*)d_in[16];
    const float* chw   = (const float*)d_in[17];
    const float* chb   = (const float*)d_in[18];
    const float* cow   = (const float*)d_in[19];
    const float* cobb  = (const float*)d_in[20];
    const int* gs_part = (const int*)d_in[21];
    const int* uv_idx  = (const int*)d_in[22];
    float* out = (float*)d_out;

    cudaFuncSetAttribute(mlp_kernel, cudaFuncAttributeMaxDynamicSharedMemorySize, MLP_SMEM);

    float *uvmap, *buf0, *buf1;
    cudaGetSymbolAddress((void**)&uvmap, g_uvmap);
    cudaGetSymbolAddress((void**)&buf0, g_buf0);
    cudaGetSymbolAddress((void**)&buf1, g_buf1);

    clear_uvmap_kernel<<<2048, 256>>>();
    partbias_kernel<<<P_N, 128>>>(latent_f, w1in, b1in, w2in, b2in);
    count_kernel<<<(G_N + 255) / 256, 256>>>(gs_part);
    offsets_kernel<<<1, 32>>>();
    scatter_kernel<<<(G_N + 255) / 256, 256>>>(gs_part);
    mlp_kernel<<<G_N / 64 + P_N, 256, MLP_SMEM>>>(latent_z, cano_xyz,
        w1in, w1hid, b1hid, w1out, b1out,
        w2in, w2hid, b2hid, w2out, b2out, uv_idx);

    dim3 cgrid(16, 16, 2);
    // x0 = conv_in(uvmap)
    conv3x3_kernel<<<cgrid, 256>>>(uvmap, HD, cinw, cinb, buf0, 0);
    // x1 = IN(conv0(relu(x0)))
    conv3x3_kernel<<<cgrid, 256>>>(buf0, CC, chw + 0 * CC * CC * 9, chb + 0 * CC, buf1, 1);
    in_stats_kernel<<<CC, 256>>>(buf1);
    // x2 = IN(conv1(relu(x1)))
    conv3x3_kernel<<<cgrid, 256>>>(buf1, CC, chw + 1 * CC * CC * 9, chb + 1 * CC, buf0, 2);
    in_stats_kernel<<<CC, 256>>>(buf0);
    // x3 = IN(conv2(relu(x2)))
    conv3x3_kernel<<<cgrid, 256>>>(buf0, CC, chw + 2 * CC * CC * 9, chb + 2 * CC, buf1, 2);
    in_stats_kernel<<<CC, 256>>>(buf1);
    // out = sigmoid(conv_out(x3))
    convout_kernel<<<dim3(16, 16, 1), 256>>>(buf1, cow, cobb, out);
}

// round 4
// speedup vs baseline: 1.5296x; 1.5296x over previous
#include <cuda_runtime.h>
#include <math.h>

#define G_N   40000
#define P_N   5
#define ZD    32
#define FD    64
#define HD    32
#define UVN   256
#define UV2   (UVN*UVN)
#define CC    64

// -------- scratch (device globals: no allocation allowed) --------
__device__ float g_uvmap[HD * UV2];          // 8 MB   CNN input
__device__ float g_buf0[CC * UV2];           // 16 MB
__device__ float g_buf1[CC * UV2];           // 16 MB
__device__ float g_bias1[P_N * 128];
__device__ float g_bias2[P_N * 128];
__device__ int   g_cnt[P_N];
__device__ int   g_cursor[P_N];
__device__ int   g_poff[P_N + 1];
__device__ int   g_order[40960];
__device__ float g_stats[2 * CC];            // mean[64], invstd[64]
// transposed tf32 conv weights: conv_in [9][32][64] then 3x hidden [9][64][64]
#define WT_IN_SZ   (9 * 32 * 64)
#define WT_HID_SZ  (9 * 64 * 64)
__device__ float g_wT[WT_IN_SZ + 3 * WT_HID_SZ];

__device__ __forceinline__ float lrelu(float x) { return x > 0.f ? x : 0.01f * x; }

__device__ __forceinline__ unsigned f2tf(float v) {
    unsigned u;
    asm("cvt.rna.tf32.f32 %0, %1;" : "=r"(u) : "f"(v));
    return u;
}

__device__ __forceinline__ void mma_tf32(float* c, const unsigned* a, const unsigned* b) {
    asm volatile(
        "mma.sync.aligned.m16n8k8.row.col.f32.tf32.tf32.f32 "
        "{%0,%1,%2,%3}, {%4,%5,%6,%7}, {%8,%9}, {%0,%1,%2,%3};"
        : "+f"(c[0]), "+f"(c[1]), "+f"(c[2]), "+f"(c[3])
        : "r"(a[0]), "r"(a[1]), "r"(a[2]), "r"(a[3]), "r"(b[0]), "r"(b[1]));
}

// ============================================================
// prep kernels
// ============================================================
__global__ void clear_uvmap_kernel() {
    int i = blockIdx.x * blockDim.x + threadIdx.x;
    float4 z = make_float4(0.f, 0.f, 0.f, 0.f);
    if (i < HD * UV2 / 4) reinterpret_cast<float4*>(g_uvmap)[i] = z;
    if (blockIdx.x == 0 && threadIdx.x < P_N) g_cnt[threadIdx.x] = 0;
}

__global__ void count_kernel(const int* __restrict__ gs_part) {
    int g = blockIdx.x * blockDim.x + threadIdx.x;
    if (g < G_N) atomicAdd(&g_cnt[gs_part[g]], 1);
}

// per-part folded bias: bias = b_in + latent_f[p] . W_in[0:64]
__global__ void partbias_kernel(const float* __restrict__ latent_f,
                                const float* __restrict__ w1in, const float* __restrict__ b1in,
                                const float* __restrict__ w2in, const float* __restrict__ b2in) {
    int p = blockIdx.x, n = threadIdx.x;
    float s1 = b1in[p * 128 + n];
    float s2 = b2in[p * 128 + n];
    for (int k = 0; k < FD; k++) {
        float f = latent_f[p * FD + k];
        s1 += f * w1in[(p * 96 + k) * 128 + n];
        s2 += f * w2in[(p * 110 + k) * 128 + n];
    }
    g_bias1[p * 128 + n] = s1;
    g_bias2[p * 128 + n] = s2;
}

__global__ void offsets_kernel() {
    if (threadIdx.x == 0) {
        int off = 0;
        for (int p = 0; p < P_N; p++) {
            g_poff[p] = off;
            off += ((g_cnt[p] + 63) >> 6) << 6;   // pad each part to 64
            g_cursor[p] = 0;
        }
        g_poff[P_N] = off;
    }
}

__global__ void scatter_kernel(const int* __restrict__ gs_part) {
    int g = blockIdx.x * blockDim.x + threadIdx.x;
    if (g < G_N) {
        int p = gs_part[g];
        int pos = g_poff[p] + atomicAdd(&g_cursor[p], 1);
        g_order[pos] = g;
    }
}

// transpose conv weights [co][ci][tap] -> [tap][ci][co], tf32-rounded
__global__ void transpose_w_kernel(const float* __restrict__ cinw,
                                   const float* __restrict__ chw) {
    int idx = blockIdx.x * blockDim.x + threadIdx.x;
    if (idx < WT_IN_SZ) {
        int co = idx & 63, t = idx >> 6;
        int ci = t % 32, tap = t / 32;
        g_wT[idx] = __uint_as_float(f2tf(cinw[(co * 32 + ci) * 9 + tap]));
    } else if (idx < WT_IN_SZ + 3 * WT_HID_SZ) {
        int r = idx - WT_IN_SZ;
        int l = r / WT_HID_SZ, i = r % WT_HID_SZ;
        int co = i & 63, t = i >> 6;
        int ci = t & 63, tap = t >> 6;
        g_wT[idx] = __uint_as_float(f2tf(chw[l * 64 * 64 * 9 + (co * 64 + ci) * 9 + tap]));
    }
}

// ============================================================
// fused per-part MLP1 + MLP2 (64 gaussians / block, 256 threads)
// ============================================================
__device__ __forceinline__ void layer128(const float* As, const float* __restrict__ Wg,
                                         const float* __restrict__ bias,
                                         float* Ws, float* Os, int K, bool act, int tid) {
    const int g0 = (tid & 15) * 4;
    const int n0 = (tid >> 4) * 8;
    float c[4][8];
#pragma unroll
    for (int j = 0; j < 8; j++) {
        float b = bias[n0 + j];
#pragma unroll
        for (int i = 0; i < 4; i++) c[i][j] = b;
    }
    for (int kt = 0; kt < K; kt += 32) {
        int kk = min(32, K - kt);
        for (int idx = tid; idx < kk * 128; idx += 256) Ws[idx] = Wg[kt * 128 + idx];
        __syncthreads();
#pragma unroll 4
        for (int k = 0; k < kk; k++) {
            float4 a  = *reinterpret_cast<const float4*>(As + (kt + k) * 64 + g0);
            float4 w0 = *reinterpret_cast<const float4*>(Ws + k * 128 + n0);
            float4 w1 = *reinterpret_cast<const float4*>(Ws + k * 128 + n0 + 4);
            float av[4] = {a.x, a.y, a.z, a.w};
            float wv[8] = {w0.x, w0.y, w0.z, w0.w, w1.x, w1.y, w1.z, w1.w};
#pragma unroll
            for (int i = 0; i < 4; i++)
#pragma unroll
                for (int j = 0; j < 8; j++) c[i][j] += av[i] * wv[j];
        }
        __syncthreads();
    }
#pragma unroll
    for (int j = 0; j < 8; j++) {
        float4 v;
        v.x = act ? lrelu(c[0][j]) : c[0][j];
        v.y = act ? lrelu(c[1][j]) : c[1][j];
        v.z = act ? lrelu(c[2][j]) : c[2][j];
        v.w = act ? lrelu(c[3][j]) : c[3][j];
        *reinterpret_cast<float4*>(Os + (n0 + j) * 64 + g0) = v;
    }
}

__global__ void __launch_bounds__(256) mlp_kernel(
    const float* __restrict__ latent_z, const float* __restrict__ cano_xyz,
    const float* __restrict__ w1in,
    const float* __restrict__ w1hid, const float* __restrict__ b1hid,
    const float* __restrict__ w1out, const float* __restrict__ b1out,
    const float* __restrict__ w2in,
    const float* __restrict__ w2hid, const float* __restrict__ b2hid,
    const float* __restrict__ w2out, const float* __restrict__ b2out,
    const int* __restrict__ uv_idx) {
    extern __shared__ float sm[];
    float* Es = sm;                     // [48][64]
    float* Ha = Es + 48 * 64;           // [128][64]
    float* Hb = Ha + 128 * 64;          // [128][64]
    float* Ws = Hb + 128 * 64;          // 4096 floats
    int*   gidxs = reinterpret_cast<int*>(Ws + 4096);
    int*   uvs   = gidxs + 64;

    const int tid = threadIdx.x;
    const int base = blockIdx.x * 64;
    if (base >= g_poff[P_N]) return;
    int p = 0;
    while (p < P_N - 1 && base >= g_poff[p + 1]) p++;
    const int seg0 = g_poff[p];
    const int cnt  = g_cnt[p];

    if (tid < 64) {
        int srow = base - seg0 + tid;
        int gi = (srow < cnt) ? g_order[base + tid] : -1;
        gidxs[tid] = gi;
        uvs[tid] = (gi >= 0) ? uv_idx[gi] : 0;
    }
    __syncthreads();

    for (int idx = tid; idx < 64 * ZD; idx += 256) {
        int g = idx >> 5, k = idx & 31;
        int gi = gidxs[g];
        Es[k * 64 + g] = (gi >= 0) ? latent_z[gi * ZD + k] : 0.f;
    }
    for (int idx = tid; idx < 64 * 3; idx += 256) {
        int g = idx / 3, k = idx - g * 3;
        int gi = gidxs[g];
        Es[(32 + k) * 64 + g] = (gi >= 0) ? cano_xyz[gi * 3 + k] : 0.f;
    }
    __syncthreads();

    // ---- MLP1 ----
    layer128(Es, w1in + (p * 96 + 64) * 128, g_bias1 + p * 128, Ws, Ha, 32, true, tid);
    layer128(Ha, w1hid + p * 2 * 16384,          b1hid + p * 2 * 128,       Ws, Hb, 128, true, tid);
    layer128(Hb, w1hid + p * 2 * 16384 + 16384,  b1hid + p * 2 * 128 + 128, Ws, Ha, 128, true, tid);

    for (int idx = tid; idx < 128 * 11; idx += 256) Ws[idx] = w1out[p * 128 * 11 + idx];
    __syncthreads();
    {
        int g = tid & 63, nb = tid >> 6;
        float s0 = 0.f, s1 = 0.f, s2 = 0.f;
        bool has2 = (nb + 8) < 11;
        for (int k = 0; k < 128; k++) {
            float a = Ha[k * 64 + g];
            s0 += a * Ws[k * 11 + nb];
            s1 += a * Ws[k * 11 + nb + 4];
            if (has2) s2 += a * Ws[k * 11 + nb + 8];
        }
        Es[(35 + nb) * 64 + g]     = s0 + b1out[p * 11 + nb];
        Es[(35 + nb + 4) * 64 + g] = s1 + b1out[p * 11 + nb + 4];
        if (has2) Es[(35 + nb + 8) * 64 + g] = s2 + b1out[p * 11 + nb + 8];
    }
    __syncthreads();

    // ---- MLP2 ----
    layer128(Es, w2in + (p * 110 + 64) * 128, g_bias2 + p * 128, Ws, Hb, 46, true, tid);
    layer128(Hb, w2hid + p * 2 * 16384,          b2hid + p * 2 * 128,       Ws, Ha, 128, true, tid);
    layer128(Ha, w2hid + p * 2 * 16384 + 16384,  b2hid + p * 2 * 128 + 128, Ws, Hb, 128, true, tid);

    for (int idx = tid; idx < 128 * 32; idx += 256) Ws[idx] = w2out[p * 128 * 32 + idx];
    __syncthreads();
    {
        const int g0 = (tid & 15) * 4;
        const int n0 = (tid >> 4) * 2;
        float c[4][2];
#pragma unroll
        for (int j = 0; j < 2; j++) {
            float b = b2out[p * 32 + n0 + j];
#pragma unroll
            for (int i = 0; i < 4; i++) c[i][j] = b;
        }
#pragma unroll 4
        for (int k = 0; k < 128; k++) {
            float4 a = *reinterpret_cast<const float4*>(Hb + k * 64 + g0);
            float w0 = Ws[k * 32 + n0], w1 = Ws[k * 32 + n0 + 1];
            float av[4] = {a.x, a.y, a.z, a.w};
#pragma unroll
            for (int i = 0; i < 4; i++) { c[i][0] += av[i] * w0; c[i][1] += av[i] * w1; }
        }
#pragma unroll
        for (int i = 0; i < 4; i++) {
            int gi = gidxs[g0 + i];
            if (gi >= 0) {
                int uv = uvs[g0 + i];
                g_uvmap[(n0 + 0) * UV2 + uv] = c[i][0];
                g_uvmap[(n0 + 1) * UV2 + uv] = c[i][1];
            }
        }
    }
}

// ============================================================
// CNN: tf32 tensor-core 3x3 conv
// Block: 8x16 pixel patch x 64 couts, 256 threads (8 warps: 4M x 2N).
// Warp tile: 32 pixels x 32 couts = 2 x 4 mma(m16n8k8) tiles.
// pre: 0 = raw, 1 = relu, 2 = instnorm+relu (applied to INPUT).
// ============================================================
__global__ void __launch_bounds__(256) conv3x3_tf32_kernel(
    const float* __restrict__ in, int cin,
    const float* __restrict__ wT,       // [9][cin][64], tf32-rounded
    const float* __restrict__ bias,
    float* __restrict__ out, int pre) {
    __shared__ float ins[10 * 18 * 12];     // [y][x][ci pad 12], 8 ci used
    __shared__ float wsm[72 * 72];          // [tap*8+ci][co pad 72], 64 co used

    const int tid  = threadIdx.x;
    const int lane = tid & 31, warp = tid >> 5;
    const int mw = warp & 3, nw = warp >> 2;      // M quadrant / N half
    const int gid = lane >> 2, tc = lane & 3;
    const int bx = blockIdx.x, by = blockIdx.y;

    float c[2][4][4] = {};

    for (int cc = 0; cc < cin; cc += 8) {
        // stage input tile: 8 ci x 10 x 18 (with halo), pre-op + tf32 round
        for (int idx = tid; idx < 1440; idx += 256) {
            int ci = idx / 180, rem = idx - ci * 180;
            int y = rem / 18, x = rem - y * 18;
            int gy = by * 8 + y - 1, gx = bx * 16 + x - 1;
            float v = 0.f;
            if ((unsigned)gy < 256u && (unsigned)gx < 256u) {
                v = in[(cc + ci) * UV2 + gy * 256 + gx];
                if (pre == 2) v = (v - g_stats[cc + ci]) * g_stats[64 + cc + ci];
                if (pre) v = fmaxf(v, 0.f);
            }
            ins[(y * 18 + x) * 12 + ci] = __uint_as_float(f2tf(v));
        }
        // stage weights: 9 taps x 8 ci x 64 co (coalesced from wT)
        for (int idx = tid; idx < 4608; idx += 256) {
            int co = idx & 63, t = idx >> 6;   // t = tap*8 + ci
            int ci = t & 7, tap = t >> 3;
            wsm[t * 72 + co] = wT[(tap * cin + cc + ci) * 64 + co];
        }
        __syncthreads();

#pragma unroll
        for (int tap = 0; tap < 9; ++tap) {
            const int ky = tap / 3, kx = tap - 3 * (tap / 3);
            unsigned b[4][2];
#pragma unroll
            for (int j = 0; j < 4; ++j) {
                int n = nw * 32 + j * 8 + gid;
                b[j][0] = __float_as_uint(wsm[(tap * 8 + tc) * 72 + n]);
                b[j][1] = __float_as_uint(wsm[(tap * 8 + tc + 4) * 72 + n]);
            }
#pragma unroll
            for (int i = 0; i < 2; ++i) {
                const int pr = 2 * mw + i + ky;           // input row in tile
                const float* rb = ins + (pr * 18 + kx) * 12;
                unsigned a[4];
                a[0] = __float_as_uint(rb[(gid)     * 12 + tc]);
                a[1] = __float_as_uint(rb[(gid + 8) * 12 + tc]);
                a[2] = __float_as_uint(rb[(gid)     * 12 + tc + 4]);
                a[3] = __float_as_uint(rb[(gid + 8) * 12 + tc + 4]);
#pragma unroll
                for (int j = 0; j < 4; ++j) mma_tf32(c[i][j], a, b[j]);
            }
        }
        __syncthreads();
    }

    // epilogue: bias + store
#pragma unroll
    for (int i = 0; i < 2; ++i) {
        const int gy = by * 8 + 2 * mw + i;
        const int gx = bx * 16;
#pragma unroll
        for (int j = 0; j < 4; ++j) {
            const int co = nw * 32 + j * 8 + 2 * tc;
            float b0 = bias[co], b1 = bias[co + 1];
            out[co * UV2 + gy * 256 + gx + gid]           = c[i][j][0] + b0;
            out[(co + 1) * UV2 + gy * 256 + gx + gid]     = c[i][j][1] + b1;
            out[co * UV2 + gy * 256 + gx + gid + 8]       = c[i][j][2] + b0;
            out[(co + 1) * UV2 + gy * 256 + gx + gid + 8] = c[i][j][3] + b1;
        }
    }
}

// conv_out: 64 -> 3, input instance-normalized (no relu), sigmoid output.
__global__ void __launch_bounds__(256) convout_kernel(
    const float* __restrict__ in,
    const float* __restrict__ w, const float* __restrict__ bias,
    float* __restrict__ out) {
    __shared__ float ins[16][18][20];
    __shared__ float wsf[3 * 144];

    const int tid = threadIdx.x;
    const int bx = blockIdx.x, by = blockIdx.y;
    const int x = tid & 15, y = tid >> 4;

    float acc[3] = {0.f, 0.f, 0.f};
    for (int cc = 0; cc < CC; cc += 16) {
        for (int idx = tid; idx < 16 * 18 * 18; idx += 256) {
            int ci = idx / 324;
            int rr = idx - ci * 324;
            int r = rr / 18, col = rr - r * 18;
            int gy = by * 16 + r - 1, gx = bx * 16 + col - 1;
            float v = 0.f;
            if ((unsigned)gy < 256u && (unsigned)gx < 256u) {
                v = in[(cc + ci) * UV2 + gy * 256 + gx];
                v = (v - g_stats[cc + ci]) * g_stats[64 + cc + ci];
            }
            ins[ci][r][col] = v;
        }
        for (int idx = tid; idx < 3 * 144; idx += 256) {
            int co = idx / 144, r = idx - co * 144;
            wsf[idx] = w[co * CC * 9 + cc * 9 + r];
        }
        __syncthreads();
        for (int ci = 0; ci < 16; ci++) {
#pragma unroll
            for (int tap = 0; tap < 9; tap++) {
                const int ky = tap / 3, kx = tap - ky * 3;
                float v = ins[ci][y + ky][x + kx];
#pragma unroll
                for (int co = 0; co < 3; co++) acc[co] += v * wsf[co * 144 + ci * 9 + tap];
            }
        }
        __syncthreads();
    }
#pragma unroll
    for (int co = 0; co < 3; co++) {
        float v = acc[co] + bias[co];
        out[co * UV2 + (by * 16 + y) * 256 + bx * 16 + x] = 1.f / (1.f + expf(-v));
    }
}

// per-channel instance-norm stats over 256x256
__global__ void in_stats_kernel(const float* __restrict__ x) {
    const int c = blockIdx.x;
    const float* p = x + c * UV2;
    float s = 0.f, q = 0.f;
    for (int i = threadIdx.x; i < UV2; i += 256) {
        float v = p[i];
        s += v; q += v * v;
    }
    __shared__ float rs[256], rq[256];
    rs[threadIdx.x] = s; rq[threadIdx.x] = q;
    __syncthreads();
    for (int o = 128; o > 0; o >>= 1) {
        if (threadIdx.x < o) { rs[threadIdx.x] += rs[threadIdx.x + o]; rq[threadIdx.x] += rq[threadIdx.x + o]; }
        __syncthreads();
    }
    if (threadIdx.x == 0) {
        float m = rs[0] * (1.f / UV2);
        float var = rq[0] * (1.f / UV2) - m * m;
        g_stats[c] = m;
        g_stats[64 + c] = rsqrtf(fmaxf(var, 0.f) + 1e-5f);
    }
}

// ============================================================
// host launch
// ============================================================
#define MLP_SMEM ((48 * 64 + 128 * 64 * 2 + 4096) * 4 + 128 * 4)

extern "C" void kernel_launch(void* const* d_in, const int* in_sizes, int n_in,
                              void* d_out, int out_size) {
    const float* latent_z = (const float*)d_in[0];
    const float* latent_f = (const float*)d_in[1];
    const float* cano_xyz = (const float*)d_in[2];
    const float* w1in  = (const float*)d_in[3];
    const float* b1in  = (const float*)d_in[4];
    const float* w1hid = (const float*)d_in[5];
    const float* b1hid = (const float*)d_in[6];
    const float* w1out = (const float*)d_in[7];
    const float* b1out = (const float*)d_in[8];
    const float* w2in  = (const float*)d_in[9];
    const float* b2in  = (const float*)d_in[10];
    const float* w2hid = (const float*)d_in[11];
    const float* b2hid = (const float*)d_in[12];
    const float* w2out = (const float*)d_in[13];
    const float* b2out = (const float*)d_in[14];
    const float* cinw  = (const float*)d_in[15];
    const float* cinb  = (const float*)d_in[16];
    const float* chw   = (const float*)d_in[17];
    const float* chb   = (const float*)d_in[18];
    const float* cow   = (const float*)d_in[19];
    const float* cobb  = (const float*)d_in[20];
    const int* gs_part = (const int*)d_in[21];
    const int* uv_idx  = (const int*)d_in[22];
    float* out = (float*)d_out;

    cudaFuncSetAttribute(mlp_kernel, cudaFuncAttributeMaxDynamicSharedMemorySize, MLP_SMEM);

    float *uvmap, *buf0, *buf1, *wT;
    cudaGetSymbolAddress((void**)&uvmap, g_uvmap);
    cudaGetSymbolAddress((void**)&buf0, g_buf0);
    cudaGetSymbolAddress((void**)&buf1, g_buf1);
    cudaGetSymbolAddress((void**)&wT, g_wT);

    // launches 1-5 (prep), 6 = mlp (ncu -s 5 captures it)
    clear_uvmap_kernel<<<2048, 256>>>();
    count_kernel<<<(G_N + 255) / 256, 256>>>(gs_part);
    partbias_kernel<<<P_N, 128>>>(latent_f, w1in, b1in, w2in, b2in);
    offsets_kernel<<<1, 32>>>();
    scatter_kernel<<<(G_N + 255) / 256, 256>>>(gs_part);
    mlp_kernel<<<G_N / 64 + P_N, 256, MLP_SMEM>>>(latent_z, cano_xyz,
        w1in, w1hid, b1hid, w1out, b1out,
        w2in, w2hid, b2hid, w2out, b2out, uv_idx);

    transpose_w_kernel<<<(WT_IN_SZ + 3 * WT_HID_SZ + 255) / 256, 256>>>(cinw, chw);

    dim3 cgrid(UVN / 16, UVN / 8);
    // x0 = conv_in(uvmap)
    conv3x3_tf32_kernel<<<cgrid, 256>>>(uvmap, HD, wT, cinb, buf0, 0);
    // x1 = IN(conv0(relu(x0)))
    conv3x3_tf32_kernel<<<cgrid, 256>>>(buf0, CC, wT + WT_IN_SZ, chb, buf1, 1);
    in_stats_kernel<<<CC, 256>>>(buf1);
    // x2 = IN(conv1(relu(x1)))
    conv3x3_tf32_kernel<<<cgrid, 256>>>(buf1, CC, wT + WT_IN_SZ + WT_HID_SZ, chb + CC, buf0, 2);
    in_stats_kernel<<<CC, 256>>>(buf0);
    // x3 = IN(conv2(relu(x2)))
    conv3x3_tf32_kernel<<<cgrid, 256>>>(buf0, CC, wT + WT_IN_SZ + 2 * WT_HID_SZ, chb + 2 * CC, buf1, 2);
    in_stats_kernel<<<CC, 256>>>(buf1);
    // out = sigmoid(conv_out(x3))
    convout_kernel<<<dim3(16, 16, 1), 256>>>(buf1, cow, cobb, out);
}

// round 5
// speedup vs baseline: 1.6430x; 1.0741x over previous
#include <cuda_runtime.h>
#include <math.h>

#define G_N   40000
#define P_N   5
#define ZD    32
#define FD    64
#define HD    32
#define UVN   256
#define UV2   (UVN*UVN)
#define CC    64

// -------- scratch (device globals: no allocation allowed) --------
__device__ float g_uvmap[HD * UV2];
__device__ float g_buf0[CC * UV2];
__device__ float g_buf1[CC * UV2];
__device__ float g_bias1[P_N * 128];
__device__ float g_bias2[P_N * 128];
__device__ int   g_cnt[P_N];
__device__ int   g_cursor[P_N];
__device__ int   g_poff[P_N + 1];
__device__ int   g_order[40960];
__device__ float g_stats[2 * CC];            // mean[64], invstd[64]
__device__ float g_ssum[2 * CC];             // sum[64], sumsq[64] accumulators
#define WT_IN_SZ   (9 * 32 * 64)
#define WT_HID_SZ  (9 * 64 * 64)
__device__ float g_wT[WT_IN_SZ + 3 * WT_HID_SZ];

__device__ __forceinline__ float lrelu(float x) { return x > 0.f ? x : 0.01f * x; }

__device__ __forceinline__ unsigned f2tf(float v) {
    unsigned u;
    asm("cvt.rna.tf32.f32 %0, %1;" : "=r"(u) : "f"(v));
    return u;
}
__device__ __forceinline__ float f2tff(float v) { return __uint_as_float(f2tf(v)); }

__device__ __forceinline__ void mma_tf32(float* c, const unsigned* a, const unsigned* b) {
    asm volatile(
        "mma.sync.aligned.m16n8k8.row.col.f32.tf32.tf32.f32 "
        "{%0,%1,%2,%3}, {%4,%5,%6,%7}, {%8,%9}, {%0,%1,%2,%3};"
        : "+f"(c[0]), "+f"(c[1]), "+f"(c[2]), "+f"(c[3])
        : "r"(a[0]), "r"(a[1]), "r"(a[2]), "r"(a[3]), "r"(b[0]), "r"(b[1]));
}

// ============================================================
// prep kernels
// ============================================================
__global__ void clear_uvmap_kernel() {
    int i = blockIdx.x * blockDim.x + threadIdx.x;
    float4 z = make_float4(0.f, 0.f, 0.f, 0.f);
    if (i < HD * UV2 / 4) reinterpret_cast<float4*>(g_uvmap)[i] = z;
    if (blockIdx.x == 0 && threadIdx.x < P_N) g_cnt[threadIdx.x] = 0;
    if (blockIdx.x == 1 && threadIdx.x < 128) g_ssum[threadIdx.x] = 0.f;
}

__global__ void count_kernel(const int* __restrict__ gs_part) {
    int g = blockIdx.x * blockDim.x + threadIdx.x;
    if (g < G_N) atomicAdd(&g_cnt[gs_part[g]], 1);
}

__global__ void partbias_kernel(const float* __restrict__ latent_f,
                                const float* __restrict__ w1in, const float* __restrict__ b1in,
                                const float* __restrict__ w2in, const float* __restrict__ b2in) {
    int p = blockIdx.x, n = threadIdx.x;
    float s1 = b1in[p * 128 + n];
    float s2 = b2in[p * 128 + n];
    for (int k = 0; k < FD; k++) {
        float f = latent_f[p * FD + k];
        s1 += f * w1in[(p * 96 + k) * 128 + n];
        s2 += f * w2in[(p * 110 + k) * 128 + n];
    }
    g_bias1[p * 128 + n] = s1;
    g_bias2[p * 128 + n] = s2;
}

__global__ void offsets_kernel() {
    if (threadIdx.x == 0) {
        int off = 0;
        for (int p = 0; p < P_N; p++) {
            g_poff[p] = off;
            off += ((g_cnt[p] + 63) >> 6) << 6;
            g_cursor[p] = 0;
        }
        g_poff[P_N] = off;
    }
}

__global__ void scatter_kernel(const int* __restrict__ gs_part) {
    int g = blockIdx.x * blockDim.x + threadIdx.x;
    if (g < G_N) {
        int p = gs_part[g];
        int pos = g_poff[p] + atomicAdd(&g_cursor[p], 1);
        g_order[pos] = g;
    }
}

// transpose conv weights [co][ci][tap] -> [tap][ci][co], tf32-rounded
__global__ void transpose_w_kernel(const float* __restrict__ cinw,
                                   const float* __restrict__ chw) {
    int idx = blockIdx.x * blockDim.x + threadIdx.x;
    if (idx < WT_IN_SZ) {
        int co = idx & 63, t = idx >> 6;
        int ci = t % 32, tap = t / 32;
        g_wT[idx] = f2tff(cinw[(co * 32 + ci) * 9 + tap]);
    } else if (idx < WT_IN_SZ + 3 * WT_HID_SZ) {
        int r = idx - WT_IN_SZ;
        int l = r / WT_HID_SZ, i = r % WT_HID_SZ;
        int co = i & 63, t = i >> 6;
        int ci = t & 63, tap = t >> 6;
        g_wT[idx] = f2tff(chw[l * 64 * 64 * 9 + (co * 64 + ci) * 9 + tap]);
    }
}

// ============================================================
// MLP: tf32 tensor-core layers
// act layout: [n][g] rows stride 72 (tf32-rounded values).
// W staging: Wc[32][136] chunks, tf32-rounded.
// 8 warps = 2M x 4N; warp tile 32g x 32n = 2x4 m16n8k8.
// ============================================================
#define AST 72
#define WST 136

__device__ __forceinline__ void layer_mma(const float* __restrict__ A,
                                          const float* __restrict__ Wg,
                                          const float* __restrict__ bias,
                                          int Kreal, int K,
                                          float* Wc, float* Out, int tid) {
    const int lane = tid & 31, warp = tid >> 5;
    const int mw = warp & 1, nw = warp >> 1;
    const int gid = lane >> 2, tc = lane & 3;

    float c[2][4][4];
#pragma unroll
    for (int j = 0; j < 4; j++) {
        int n0 = nw * 32 + j * 8;
        float b0 = bias[n0 + 2 * tc], b1 = bias[n0 + 2 * tc + 1];
#pragma unroll
        for (int i = 0; i < 2; i++) { c[i][j][0] = b0; c[i][j][1] = b1; c[i][j][2] = b0; c[i][j][3] = b1; }
    }

    for (int kc = 0; kc < K; kc += 32) {
        int kk = min(32, K - kc);
        for (int idx = tid; idx < kk * 128; idx += 256) {
            int k = idx >> 7, n = idx & 127;
            float v = (kc + k < Kreal) ? Wg[(kc + k) * 128 + n] : 0.f;
            Wc[k * WST + n] = f2tff(v);
        }
        __syncthreads();
        for (int ks = 0; ks < kk; ks += 8) {
            unsigned a[2][4];
#pragma unroll
            for (int i = 0; i < 2; i++) {
                const int m0 = mw * 32 + 16 * i;
                const float* Ab = A + (kc + ks) * AST + m0;
                a[i][0] = __float_as_uint(Ab[tc * AST + gid]);
                a[i][1] = __float_as_uint(Ab[tc * AST + gid + 8]);
                a[i][2] = __float_as_uint(Ab[(tc + 4) * AST + gid]);
                a[i][3] = __float_as_uint(Ab[(tc + 4) * AST + gid + 8]);
            }
#pragma unroll
            for (int j = 0; j < 4; j++) {
                const int n0 = nw * 32 + 8 * j;
                unsigned b[2];
                b[0] = __float_as_uint(Wc[(ks + tc) * WST + n0 + gid]);
                b[1] = __float_as_uint(Wc[(ks + tc + 4) * WST + n0 + gid]);
                mma_tf32(c[0][j], a[0], b);
                mma_tf32(c[1][j], a[1], b);
            }
        }
        __syncthreads();
    }

    // epilogue: leaky-relu + tf32-round + store [n][g]
#pragma unroll
    for (int i = 0; i < 2; i++) {
        const int m0 = mw * 32 + 16 * i;
#pragma unroll
        for (int j = 0; j < 4; j++) {
            const int n0 = nw * 32 + 8 * j + 2 * tc;
            Out[n0 * AST + m0 + gid]           = f2tff(lrelu(c[i][j][0]));
            Out[(n0 + 1) * AST + m0 + gid]     = f2tff(lrelu(c[i][j][1]));
            Out[n0 * AST + m0 + gid + 8]       = f2tff(lrelu(c[i][j][2]));
            Out[(n0 + 1) * AST + m0 + gid + 8] = f2tff(lrelu(c[i][j][3]));
        }
    }
}

__global__ void __launch_bounds__(256) mlp_kernel(
    const float* __restrict__ latent_z, const float* __restrict__ cano_xyz,
    const float* __restrict__ w1in,
    const float* __restrict__ w1hid, const float* __restrict__ b1hid,
    const float* __restrict__ w1out, const float* __restrict__ b1out,
    const float* __restrict__ w2in,
    const float* __restrict__ w2hid, const float* __restrict__ b2hid,
    const float* __restrict__ w2out, const float* __restrict__ b2out,
    const int* __restrict__ uv_idx) {
    extern __shared__ float sm[];
    float* Es = sm;                      // [48][72]: 0-31 z, 32-34 xyz, 35-45 attrs, 46-47 zero
    float* Ha = Es + 48 * AST;           // [128][72]
    float* Hb = Ha + 128 * AST;          // [128][72]
    float* Wc = Hb + 128 * AST;          // [32][136] = 4352 floats (also scalar W buf)
    int*   gidxs = reinterpret_cast<int*>(Wc + 32 * WST);
    int*   uvs   = gidxs + 64;

    const int tid = threadIdx.x;
    const int base = blockIdx.x * 64;
    if (base >= g_poff[P_N]) return;
    int p = 0;
    while (p < P_N - 1 && base >= g_poff[p + 1]) p++;
    const int seg0 = g_poff[p];
    const int cnt  = g_cnt[p];

    if (tid < 64) {
        int srow = base - seg0 + tid;
        int gi = (srow < cnt) ? g_order[base + tid] : -1;
        gidxs[tid] = gi;
        uvs[tid] = (gi >= 0) ? uv_idx[gi] : 0;
    }
    __syncthreads();

    for (int idx = tid; idx < 64 * ZD; idx += 256) {
        int g = idx >> 5, k = idx & 31;
        int gi = gidxs[g];
        Es[k * AST + g] = (gi >= 0) ? f2tff(latent_z[gi * ZD + k]) : 0.f;
    }
    for (int idx = tid; idx < 64 * 3; idx += 256) {
        int g = idx / 3, k = idx - g * 3;
        int gi = gidxs[g];
        Es[(32 + k) * AST + g] = (gi >= 0) ? f2tff(cano_xyz[gi * 3 + k]) : 0.f;
    }
    for (int idx = tid; idx < 2 * AST; idx += 256) Es[46 * AST + idx] = 0.f;
    __syncthreads();

    // ---- MLP1 ----
    layer_mma(Es, w1in + (p * 96 + 64) * 128, g_bias1 + p * 128, 32, 32, Wc, Ha, tid);
    layer_mma(Ha, w1hid + p * 2 * 16384,         b1hid + p * 2 * 128,       128, 128, Wc, Hb, tid);
    layer_mma(Hb, w1hid + p * 2 * 16384 + 16384, b1hid + p * 2 * 128 + 128, 128, 128, Wc, Ha, tid);

    // attrs (N=11) scalar from Ha -> Es rows 35..45 (tf32-rounded)
    for (int idx = tid; idx < 128 * 11; idx += 256) Wc[idx] = w1out[p * 128 * 11 + idx];
    __syncthreads();
    {
        int g = tid & 63, nb = tid >> 6;
        float s0 = 0.f, s1 = 0.f, s2 = 0.f;
        bool has2 = (nb + 8) < 11;
        for (int k = 0; k < 128; k++) {
            float a = Ha[k * AST + g];
            s0 += a * Wc[k * 11 + nb];
            s1 += a * Wc[k * 11 + nb + 4];
            if (has2) s2 += a * Wc[k * 11 + nb + 8];
        }
        Es[(35 + nb) * AST + g]     = f2tff(s0 + b1out[p * 11 + nb]);
        Es[(35 + nb + 4) * AST + g] = f2tff(s1 + b1out[p * 11 + nb + 4]);
        if (has2) Es[(35 + nb + 8) * AST + g] = f2tff(s2 + b1out[p * 11 + nb + 8]);
    }
    __syncthreads();

    // ---- MLP2 ---- (K=46 padded to 48)
    layer_mma(Es, w2in + (p * 110 + 64) * 128, g_bias2 + p * 128, 46, 48, Wc, Hb, tid);
    layer_mma(Hb, w2hid + p * 2 * 16384,         b2hid + p * 2 * 128,       128, 128, Wc, Ha, tid);
    layer_mma(Ha, w2hid + p * 2 * 16384 + 16384, b2hid + p * 2 * 128 + 128, 128, 128, Wc, Hb, tid);

    // final N=32 + scatter
    for (int idx = tid; idx < 128 * 32; idx += 256) Wc[idx] = w2out[p * 128 * 32 + idx];
    __syncthreads();
    {
        const int g0 = (tid & 15) * 4;
        const int n0 = (tid >> 4) * 2;
        float c[4][2];
#pragma unroll
        for (int j = 0; j < 2; j++) {
            float b = b2out[p * 32 + n0 + j];
#pragma unroll
            for (int i = 0; i < 4; i++) c[i][j] = b;
        }
#pragma unroll 4
        for (int k = 0; k < 128; k++) {
            float4 a = *reinterpret_cast<const float4*>(Hb + k * AST + g0);
            float w0 = Wc[k * 32 + n0], w1 = Wc[k * 32 + n0 + 1];
            float av[4] = {a.x, a.y, a.z, a.w};
#pragma unroll
            for (int i = 0; i < 4; i++) { c[i][0] += av[i] * w0; c[i][1] += av[i] * w1; }
        }
#pragma unroll
        for (int i = 0; i < 4; i++) {
            int gi = gidxs[g0 + i];
            if (gi >= 0) {
                int uv = uvs[g0 + i];
                g_uvmap[(n0 + 0) * UV2 + uv] = c[i][0];
                g_uvmap[(n0 + 1) * UV2 + uv] = c[i][1];
            }
        }
    }
}

// ============================================================
// CNN: tf32 tensor-core 3x3 conv (+ fused instance-norm stats)
// ============================================================
__global__ void __launch_bounds__(256) conv3x3_tf32_kernel(
    const float* __restrict__ in, int cin,
    const float* __restrict__ wT,
    const float* __restrict__ bias,
    float* __restrict__ out, int pre, int do_stats) {
    __shared__ float ins[10 * 18 * 12];
    __shared__ float wsm[72 * 72];

    const int tid  = threadIdx.x;
    const int lane = tid & 31, warp = tid >> 5;
    const int mw = warp & 3, nw = warp >> 2;
    const int gid = lane >> 2, tc = lane & 3;
    const int bx = blockIdx.x, by = blockIdx.y;

    float c[2][4][4] = {};

    for (int cc = 0; cc < cin; cc += 8) {
        for (int idx = tid; idx < 1440; idx += 256) {
            int ci = idx / 180, rem = idx - ci * 180;
            int y = rem / 18, x = rem - y * 18;
            int gy = by * 8 + y - 1, gx = bx * 16 + x - 1;
            float v = 0.f;
            if ((unsigned)gy < 256u && (unsigned)gx < 256u) {
                v = in[(cc + ci) * UV2 + gy * 256 + gx];
                if (pre == 2) v = (v - g_stats[cc + ci]) * g_stats[64 + cc + ci];
                if (pre) v = fmaxf(v, 0.f);
            }
            ins[(y * 18 + x) * 12 + ci] = f2tff(v);
        }
        for (int idx = tid; idx < 4608; idx += 256) {
            int co = idx & 63, t = idx >> 6;
            int ci = t & 7, tap = t >> 3;
            wsm[t * 72 + co] = wT[(tap * cin + cc + ci) * 64 + co];
        }
        __syncthreads();

#pragma unroll
        for (int tap = 0; tap < 9; ++tap) {
            const int ky = tap / 3, kx = tap - 3 * (tap / 3);
            unsigned b[4][2];
#pragma unroll
            for (int j = 0; j < 4; ++j) {
                int n = nw * 32 + j * 8 + gid;
                b[j][0] = __float_as_uint(wsm[(tap * 8 + tc) * 72 + n]);
                b[j][1] = __float_as_uint(wsm[(tap * 8 + tc + 4) * 72 + n]);
            }
#pragma unroll
            for (int i = 0; i < 2; ++i) {
                const int pr = 2 * mw + i + ky;
                const float* rb = ins + (pr * 18 + kx) * 12;
                unsigned a[4];
                a[0] = __float_as_uint(rb[(gid)     * 12 + tc]);
                a[1] = __float_as_uint(rb[(gid + 8) * 12 + tc]);
                a[2] = __float_as_uint(rb[(gid)     * 12 + tc + 4]);
                a[3] = __float_as_uint(rb[(gid + 8) * 12 + tc + 4]);
#pragma unroll
                for (int j = 0; j < 4; ++j) mma_tf32(c[i][j], a, b[j]);
            }
        }
        __syncthreads();
    }

    // epilogue: bias + store + (optional) per-channel sum/sumsq accumulation
#pragma unroll
    for (int j = 0; j < 4; ++j) {
        const int co = nw * 32 + j * 8 + 2 * tc;
        const float b0 = bias[co], b1 = bias[co + 1];
        float s0 = 0.f, q0 = 0.f, s1 = 0.f, q1 = 0.f;
#pragma unroll
        for (int i = 0; i < 2; ++i) {
            const int gy = by * 8 + 2 * mw + i;
            const int gx = bx * 16;
            float v0 = c[i][j][0] + b0;
            float v1 = c[i][j][1] + b1;
            float v2 = c[i][j][2] + b0;
            float v3 = c[i][j][3] + b1;
            out[co * UV2 + gy * 256 + gx + gid]           = v0;
            out[(co + 1) * UV2 + gy * 256 + gx + gid]     = v1;
            out[co * UV2 + gy * 256 + gx + gid + 8]       = v2;
            out[(co + 1) * UV2 + gy * 256 + gx + gid + 8] = v3;
            s0 += v0 + v2; q0 += v0 * v0 + v2 * v2;
            s1 += v1 + v3; q1 += v1 * v1 + v3 * v3;
        }
        if (do_stats) {
#pragma unroll
            for (int off = 4; off < 32; off <<= 1) {
                s0 += __shfl_xor_sync(0xffffffffu, s0, off);
                q0 += __shfl_xor_sync(0xffffffffu, q0, off);
                s1 += __shfl_xor_sync(0xffffffffu, s1, off);
                q1 += __shfl_xor_sync(0xffffffffu, q1, off);
            }
            if (gid == 0) {
                atomicAdd(&g_ssum[co], s0);
                atomicAdd(&g_ssum[64 + co], q0);
                atomicAdd(&g_ssum[co + 1], s1);
                atomicAdd(&g_ssum[64 + co + 1], q1);
            }
        }
    }
}

// finalize instance-norm stats from accumulators, reset accumulators
__global__ void finalize_stats_kernel() {
    int c = threadIdx.x;   // 0..63
    float s = g_ssum[c], q = g_ssum[64 + c];
    float m = s * (1.f / UV2);
    float var = q * (1.f / UV2) - m * m;
    g_stats[c] = m;
    g_stats[64 + c] = rsqrtf(fmaxf(var, 0.f) + 1e-5f);
    g_ssum[c] = 0.f;
    g_ssum[64 + c] = 0.f;
}

// conv_out: 64 -> 3, input instance-normalized (no relu), sigmoid output.
__global__ void __launch_bounds__(256) convout_kernel(
    const float* __restrict__ in,
    const float* __restrict__ w, const float* __restrict__ bias,
    float* __restrict__ out) {
    __shared__ float ins[16][18][20];
    __shared__ float wsf[3 * 144];

    const int tid = threadIdx.x;
    const int bx = blockIdx.x, by = blockIdx.y;
    const int x = tid & 15, y = tid >> 4;

    float acc[3] = {0.f, 0.f, 0.f};
    for (int cc = 0; cc < CC; cc += 16) {
        for (int idx = tid; idx < 16 * 18 * 18; idx += 256) {
            int ci = idx / 324;
            int rr = idx - ci * 324;
            int r = rr / 18, col = rr - r * 18;
            int gy = by * 16 + r - 1, gx = bx * 16 + col - 1;
            float v = 0.f;
            if ((unsigned)gy < 256u && (unsigned)gx < 256u) {
                v = in[(cc + ci) * UV2 + gy * 256 + gx];
                v = (v - g_stats[cc + ci]) * g_stats[64 + cc + ci];
            }
            ins[ci][r][col] = v;
        }
        for (int idx = tid; idx < 3 * 144; idx += 256) {
            int co = idx / 144, r = idx - co * 144;
            wsf[idx] = w[co * CC * 9 + cc * 9 + r];
        }
        __syncthreads();
        for (int ci = 0; ci < 16; ci++) {
#pragma unroll
            for (int tap = 0; tap < 9; tap++) {
                const int ky = tap / 3, kx = tap - ky * 3;
                float v = ins[ci][y + ky][x + kx];
#pragma unroll
                for (int co = 0; co < 3; co++) acc[co] += v * wsf[co * 144 + ci * 9 + tap];
            }
        }
        __syncthreads();
    }
#pragma unroll
    for (int co = 0; co < 3; co++) {
        float v = acc[co] + bias[co];
        out[co * UV2 + (by * 16 + y) * 256 + bx * 16 + x] = 1.f / (1.f + expf(-v));
    }
}

// ============================================================
// host launch
// ============================================================
#define MLP_SMEM ((48 * AST + 2 * 128 * AST + 32 * WST) * 4 + 128 * 4 + 256)

extern "C" void kernel_launch(void* const* d_in, const int* in_sizes, int n_in,
                              void* d_out, int out_size) {
    const float* latent_z = (const float*)d_in[0];
    const float* latent_f = (const float*)d_in[1];
    const float* cano_xyz = (const float*)d_in[2];
    const float* w1in  = (const float*)d_in[3];
    const float* b1in  = (const float*)d_in[4];
    const float* w1hid = (const float*)d_in[5];
    const float* b1hid = (const float*)d_in[6];
    const float* w1out = (const float*)d_in[7];
    const float* b1out = (const float*)d_in[8];
    const float* w2in  = (const float*)d_in[9];
    const float* b2in  = (const float*)d_in[10];
    const float* w2hid = (const float*)d_in[11];
    const float* b2hid = (const float*)d_in[12];
    const float* w2out = (const float*)d_in[13];
    const float* b2out = (const float*)d_in[14];
    const float* cinw  = (const float*)d_in[15];
    const float* cinb  = (const float*)d_in[16];
    const float* chw   = (const float*)d_in[17];
    const float* chb   = (const float*)d_in[18];
    const float* cow   = (const float*)d_in[19];
    const float* cobb  = (const float*)d_in[20];
    const int* gs_part = (const int*)d_in[21];
    const int* uv_idx  = (const int*)d_in[22];
    float* out = (float*)d_out;

    cudaFuncSetAttribute(mlp_kernel, cudaFuncAttributeMaxDynamicSharedMemorySize, MLP_SMEM);

    float *uvmap, *buf0, *buf1, *wT;
    cudaGetSymbolAddress((void**)&uvmap, g_uvmap);
    cudaGetSymbolAddress((void**)&buf0, g_buf0);
    cudaGetSymbolAddress((void**)&buf1, g_buf1);
    cudaGetSymbolAddress((void**)&wT, g_wT);

    clear_uvmap_kernel<<<2048, 256>>>();
    count_kernel<<<(G_N + 255) / 256, 256>>>(gs_part);
    partbias_kernel<<<P_N, 128>>>(latent_f, w1in, b1in, w2in, b2in);
    offsets_kernel<<<1, 32>>>();
    scatter_kernel<<<(G_N + 255) / 256, 256>>>(gs_part);
    mlp_kernel<<<G_N / 64 + P_N, 256, MLP_SMEM>>>(latent_z, cano_xyz,
        w1in, w1hid, b1hid, w1out, b1out,
        w2in, w2hid, b2hid, w2out, b2out, uv_idx);

    transpose_w_kernel<<<(WT_IN_SZ + 3 * WT_HID_SZ + 255) / 256, 256>>>(cinw, chw);

    dim3 cgrid(UVN / 16, UVN / 8);
    // x0 = conv_in(uvmap)
    conv3x3_tf32_kernel<<<cgrid, 256>>>(uvmap, HD, wT, cinb, buf0, 0, 0);
    // x1 = IN(conv0(relu(x0)))
    conv3x3_tf32_kernel<<<cgrid, 256>>>(buf0, CC, wT + WT_IN_SZ, chb, buf1, 1, 1);
    finalize_stats_kernel<<<1, 64>>>();
    // x2 = IN(conv1(relu(x1)))
    conv3x3_tf32_kernel<<<cgrid, 256>>>(buf1, CC, wT + WT_IN_SZ + WT_HID_SZ, chb + CC, buf0, 2, 1);
    finalize_stats_kernel<<<1, 64>>>();
    // x3 = IN(conv2(relu(x2)))
    conv3x3_tf32_kernel<<<cgrid, 256>>>(buf0, CC, wT + WT_IN_SZ + 2 * WT_HID_SZ, chb + 2 * CC, buf1, 2, 1);
    finalize_stats_kernel<<<1, 64>>>();
    // out = sigmoid(conv_out(x3))
    convout_kernel<<<dim3(16, 16, 1), 256>>>(buf1, cow, cobb, out);
}

// round 8
// speedup vs baseline: 2.0082x; 1.2223x over previous
#include <cuda_runtime.h>
#include <math.h>

#define G_N   40000
#define P_N   5
#define ZD    32
#define FD    64
#define HD    32
#define UVN   256
#define UV2   (UVN*UVN)
#define CC    64

// -------- scratch (device globals) --------
__device__ float g_uvmap[HD * UV2];
__device__ float g_buf0[CC * UV2];
__device__ float g_buf1[CC * UV2];
__device__ float g_bias1[P_N * 128];
__device__ float g_bias2[P_N * 128];
__device__ int   g_cnt[P_N];
__device__ int   g_cursor[P_N];
__device__ int   g_poff[P_N + 1];
__device__ int   g_order[40960];
__device__ float g_stats[2 * CC];            // mean[64], invstd[64]
__device__ float g_ssum[2 * CC];             // sum/sumsq accumulators (zero at rest)
#define WT_IN_SZ   (9 * 32 * 64)
#define WT_HID_SZ  (9 * 64 * 64)
#define WT_OUT_SZ  (9 * 64 * 8)
__device__ float g_wT[WT_IN_SZ + 3 * WT_HID_SZ];
__device__ float g_wTo[WT_OUT_SZ];

__device__ __forceinline__ float lrelu(float x) { return x > 0.f ? x : 0.01f * x; }

__device__ __forceinline__ unsigned f2tf(float v) {
    unsigned u;
    asm("cvt.rna.tf32.f32 %0, %1;" : "=r"(u) : "f"(v));
    return u;
}
__device__ __forceinline__ float f2tff(float v) { return __uint_as_float(f2tf(v)); }

__device__ __forceinline__ void mma_tf32(float* c, const unsigned* a, const unsigned* b) {
    asm volatile(
        "mma.sync.aligned.m16n8k8.row.col.f32.tf32.tf32.f32 "
        "{%0,%1,%2,%3}, {%4,%5,%6,%7}, {%8,%9}, {%0,%1,%2,%3};"
        : "+f"(c[0]), "+f"(c[1]), "+f"(c[2]), "+f"(c[3])
        : "r"(a[0]), "r"(a[1]), "r"(a[2]), "r"(a[3]), "r"(b[0]), "r"(b[1]));
}

// ============================================================
// prep kernels
// ============================================================
// launch 1: clear uvmap + count parts (g_cnt zeroed by previous replay's convout)
__global__ void clearcount_kernel(const int* __restrict__ gs_part) {
    int i = blockIdx.x * blockDim.x + threadIdx.x;
    float4 z = make_float4(0.f, 0.f, 0.f, 0.f);
    if (i < HD * UV2 / 4) reinterpret_cast<float4*>(g_uvmap)[i] = z;
    if (i < G_N) atomicAdd(&g_cnt[gs_part[i]], 1);
}

// launch 2: blocks 0-4 = per-part folded bias; block 5 = offsets
__global__ void partbias_offsets_kernel(const float* __restrict__ latent_f,
                                        const float* __restrict__ w1in, const float* __restrict__ b1in,
                                        const float* __restrict__ w2in, const float* __restrict__ b2in) {
    if (blockIdx.x < 5) {
        int p = blockIdx.x, n = threadIdx.x;
        float s1 = b1in[p * 128 + n];
        float s2 = b2in[p * 128 + n];
        for (int k = 0; k < FD; k++) {
            float f = latent_f[p * FD + k];
            s1 += f * w1in[(p * 96 + k) * 128 + n];
            s2 += f * w2in[(p * 110 + k) * 128 + n];
        }
        g_bias1[p * 128 + n] = s1;
        g_bias2[p * 128 + n] = s2;
    } else if (threadIdx.x == 0) {
        int off = 0;
        for (int p = 0; p < P_N; p++) {
            g_poff[p] = off;
            off += ((g_cnt[p] + 63) >> 6) << 6;
            g_cursor[p] = 0;
        }
        g_poff[P_N] = off;
    }
}

// launch 3
__global__ void scatter_kernel(const int* __restrict__ gs_part) {
    int g = blockIdx.x * blockDim.x + threadIdx.x;
    if (g < G_N) {
        int p = gs_part[g];
        int pos = g_poff[p] + atomicAdd(&g_cursor[p], 1);
        g_order[pos] = g;
    }
}

// launch 5: transpose conv weights [co][ci][tap] -> [tap][ci][co], tf32-rounded
__global__ void transpose_w_kernel(const float* __restrict__ cinw,
                                   const float* __restrict__ chw,
                                   const float* __restrict__ cow) {
    int idx = blockIdx.x * blockDim.x + threadIdx.x;
    if (idx < WT_IN_SZ) {
        int co = idx & 63, t = idx >> 6;
        int ci = t % 32, tap = t / 32;
        g_wT[idx] = f2tff(cinw[(co * 32 + ci) * 9 + tap]);
    } else if (idx < WT_IN_SZ + 3 * WT_HID_SZ) {
        int r = idx - WT_IN_SZ;
        int l = r / WT_HID_SZ, i = r % WT_HID_SZ;
        int co = i & 63, t = i >> 6;
        int ci = t & 63, tap = t >> 6;
        g_wT[idx] = f2tff(chw[l * 64 * 64 * 9 + (co * 64 + ci) * 9 + tap]);
    } else if (idx < WT_IN_SZ + 3 * WT_HID_SZ + WT_OUT_SZ) {
        int r = idx - WT_IN_SZ - 3 * WT_HID_SZ;
        int co = r & 7, t = r >> 3;         // t = tap*64 + ci
        int ci = t & 63, tap = t >> 6;
        g_wTo[r] = (co < 3) ? f2tff(cow[(co * 64 + ci) * 9 + tap]) : 0.f;
    }
}

// ============================================================
// MLP: tf32 tensor-core layers (launch 4 — ncu capture slot)
// ============================================================
#define AST 72
#define WST 136

__device__ __forceinline__ void layer_mma(const float* __restrict__ A,
                                          const float* __restrict__ Wg,
                                          const float* __restrict__ bias,
                                          int Kreal, int K,
                                          float* Wc, float* Out, int tid) {
    const int lane = tid & 31, warp = tid >> 5;
    const int mw = warp & 1, nw = warp >> 1;
    const int gid = lane >> 2, tc = lane & 3;

    float c[2][4][4];
#pragma unroll
    for (int j = 0; j < 4; j++) {
        int n0 = nw * 32 + j * 8;
        float b0 = bias[n0 + 2 * tc], b1 = bias[n0 + 2 * tc + 1];
#pragma unroll
        for (int i = 0; i < 2; i++) { c[i][j][0] = b0; c[i][j][1] = b1; c[i][j][2] = b0; c[i][j][3] = b1; }
    }

    for (int kc = 0; kc < K; kc += 32) {
        int kk = min(32, K - kc);
        for (int idx = tid; idx < kk * 128; idx += 256) {
            int k = idx >> 7, n = idx & 127;
            float v = (kc + k < Kreal) ? Wg[(kc + k) * 128 + n] : 0.f;
            Wc[k * WST + n] = f2tff(v);
        }
        __syncthreads();
        for (int ks = 0; ks < kk; ks += 8) {
            unsigned a[2][4];
#pragma unroll
            for (int i = 0; i < 2; i++) {
                const int m0 = mw * 32 + 16 * i;
                const float* Ab = A + (kc + ks) * AST + m0;
                a[i][0] = __float_as_uint(Ab[tc * AST + gid]);
                a[i][1] = __float_as_uint(Ab[tc * AST + gid + 8]);
                a[i][2] = __float_as_uint(Ab[(tc + 4) * AST + gid]);
                a[i][3] = __float_as_uint(Ab[(tc + 4) * AST + gid + 8]);
            }
#pragma unroll
            for (int j = 0; j < 4; j++) {
                const int n0 = nw * 32 + 8 * j;
                unsigned b[2];
                b[0] = __float_as_uint(Wc[(ks + tc) * WST + n0 + gid]);
                b[1] = __float_as_uint(Wc[(ks + tc + 4) * WST + n0 + gid]);
                mma_tf32(c[0][j], a[0], b);
                mma_tf32(c[1][j], a[1], b);
            }
        }
        __syncthreads();
    }

#pragma unroll
    for (int i = 0; i < 2; i++) {
        const int m0 = mw * 32 + 16 * i;
#pragma unroll
        for (int j = 0; j < 4; j++) {
            const int n0 = nw * 32 + 8 * j + 2 * tc;
            Out[n0 * AST + m0 + gid]           = f2tff(lrelu(c[i][j][0]));
            Out[(n0 + 1) * AST + m0 + gid]     = f2tff(lrelu(c[i][j][1]));
            Out[n0 * AST + m0 + gid + 8]       = f2tff(lrelu(c[i][j][2]));
            Out[(n0 + 1) * AST + m0 + gid + 8] = f2tff(lrelu(c[i][j][3]));
        }
    }
}

__global__ void __launch_bounds__(256) mlp_kernel(
    const float* __restrict__ latent_z, const float* __restrict__ cano_xyz,
    const float* __restrict__ w1in,
    const float* __restrict__ w1hid, const float* __restrict__ b1hid,
    const float* __restrict__ w1out, const float* __restrict__ b1out,
    const float* __restrict__ w2in,
    const float* __restrict__ w2hid, const float* __restrict__ b2hid,
    const float* __restrict__ w2out, const float* __restrict__ b2out,
    const int* __restrict__ uv_idx) {
    extern __shared__ float sm[];
    float* Es = sm;                      // [48][72]
    float* Ha = Es + 48 * AST;           // [128][72]
    float* Hb = Ha + 128 * AST;          // [128][72]
    float* Wc = Hb + 128 * AST;          // [32][136]
    int*   gidxs = reinterpret_cast<int*>(Wc + 32 * WST);
    int*   uvs   = gidxs + 64;

    const int tid = threadIdx.x;
    const int base = blockIdx.x * 64;
    if (base >= g_poff[P_N]) return;
    int p = 0;
    while (p < P_N - 1 && base >= g_poff[p + 1]) p++;
    const int seg0 = g_poff[p];
    const int cnt  = g_cnt[p];

    if (tid < 64) {
        int srow = base - seg0 + tid;
        int gi = (srow < cnt) ? g_order[base + tid] : -1;
        gidxs[tid] = gi;
        uvs[tid] = (gi >= 0) ? uv_idx[gi] : 0;
    }
    __syncthreads();

    for (int idx = tid; idx < 64 * ZD; idx += 256) {
        int g = idx >> 5, k = idx & 31;
        int gi = gidxs[g];
        Es[k * AST + g] = (gi >= 0) ? f2tff(latent_z[gi * ZD + k]) : 0.f;
    }
    for (int idx = tid; idx < 64 * 3; idx += 256) {
        int g = idx / 3, k = idx - g * 3;
        int gi = gidxs[g];
        Es[(32 + k) * AST + g] = (gi >= 0) ? f2tff(cano_xyz[gi * 3 + k]) : 0.f;
    }
    for (int idx = tid; idx < 2 * AST; idx += 256) Es[46 * AST + idx] = 0.f;
    __syncthreads();

    // ---- MLP1 ----
    layer_mma(Es, w1in + (p * 96 + 64) * 128, g_bias1 + p * 128, 32, 32, Wc, Ha, tid);
    layer_mma(Ha, w1hid + p * 2 * 16384,         b1hid + p * 2 * 128,       128, 128, Wc, Hb, tid);
    layer_mma(Hb, w1hid + p * 2 * 16384 + 16384, b1hid + p * 2 * 128 + 128, 128, 128, Wc, Ha, tid);

    for (int idx = tid; idx < 128 * 11; idx += 256) Wc[idx] = w1out[p * 128 * 11 + idx];
    __syncthreads();
    {
        int g = tid & 63, nb = tid >> 6;
        float s0 = 0.f, s1 = 0.f, s2 = 0.f;
        bool has2 = (nb + 8) < 11;
        for (int k = 0; k < 128; k++) {
            float a = Ha[k * AST + g];
            s0 += a * Wc[k * 11 + nb];
            s1 += a * Wc[k * 11 + nb + 4];
            if (has2) s2 += a * Wc[k * 11 + nb + 8];
        }
        Es[(35 + nb) * AST + g]     = f2tff(s0 + b1out[p * 11 + nb]);
        Es[(35 + nb + 4) * AST + g] = f2tff(s1 + b1out[p * 11 + nb + 4]);
        if (has2) Es[(35 + nb + 8) * AST + g] = f2tff(s2 + b1out[p * 11 + nb + 8]);
    }
    __syncthreads();

    // ---- MLP2 ----
    layer_mma(Es, w2in + (p * 110 + 64) * 128, g_bias2 + p * 128, 46, 48, Wc, Hb, tid);
    layer_mma(Hb, w2hid + p * 2 * 16384,         b2hid + p * 2 * 128,       128, 128, Wc, Ha, tid);
    layer_mma(Ha, w2hid + p * 2 * 16384 + 16384, b2hid + p * 2 * 128 + 128, 128, 128, Wc, Hb, tid);

    for (int idx = tid; idx < 128 * 32; idx += 256) Wc[idx] = w2out[p * 128 * 32 + idx];
    __syncthreads();
    {
        const int g0 = (tid & 15) * 4;
        const int n0 = (tid >> 4) * 2;
        float c[4][2];
#pragma unroll
        for (int j = 0; j < 2; j++) {
            float b = b2out[p * 32 + n0 + j];
#pragma unroll
            for (int i = 0; i < 4; i++) c[i][j] = b;
        }
#pragma unroll 4
        for (int k = 0; k < 128; k++) {
            float4 a = *reinterpret_cast<const float4*>(Hb + k * AST + g0);
            float w0 = Wc[k * 32 + n0], w1 = Wc[k * 32 + n0 + 1];
            float av[4] = {a.x, a.y, a.z, a.w};
#pragma unroll
            for (int i = 0; i < 4; i++) { c[i][0] += av[i] * w0; c[i][1] += av[i] * w1; }
        }
#pragma unroll
        for (int i = 0; i < 4; i++) {
            int gi = gidxs[g0 + i];
            if (gi >= 0) {
                int uv = uvs[g0 + i];
                g_uvmap[(n0 + 0) * UV2 + uv] = c[i][0];
                g_uvmap[(n0 + 1) * UV2 + uv] = c[i][1];
            }
        }
    }
}

// ============================================================
// CNN: tf32 3x3 conv, 16x16 pixel tile x 64 couts per block.
// 8 warps = 4 M-quadrants x 2 N-halves; warp = 4 m16 x 4 n8 tiles.
// Paired-k smem layouts, float2 LDS (conflict-free).
// pre: 0 raw, 1 relu, 2 instnorm+relu.
// ============================================================
__global__ void __launch_bounds__(256) conv3x3_tf32_kernel(
    const float* __restrict__ in, int cin,
    const float* __restrict__ wT,
    const float* __restrict__ bias,
    float* __restrict__ out, int pre, int do_stats) {
    __shared__ __align__(16) float ins2[18 * 18 * 8];      // [pixel][tc*2+h], ci=tc+4h
    __shared__ __align__(16) float wsm2[9 * 4 * WST];      // [(tap*4+tc)][2co+h]

    const int tid  = threadIdx.x;
    const int lane = tid & 31, warp = tid >> 5;
    const int mw = warp & 3, nw = warp >> 2;
    const int gid = lane >> 2, tc = lane & 3;
    const int bx = blockIdx.x, by = blockIdx.y;

    float c[4][4][4] = {};

    for (int cc = 0; cc < cin; cc += 8) {
        // stage input: 8 ci x 18x18 (halo), pre-op + tf32, paired-k layout
        for (int idx = tid; idx < 2592; idx += 256) {
            int ci = idx / 324, rem = idx - ci * 324;
            int y = rem / 18, x = rem - y * 18;
            int gy = by * 16 + y - 1, gx = bx * 16 + x - 1;
            float v = 0.f;
            if ((unsigned)gy < 256u && (unsigned)gx < 256u) {
                v = in[(cc + ci) * UV2 + gy * 256 + gx];
                if (pre == 2) v = (v - g_stats[cc + ci]) * g_stats[64 + cc + ci];
                if (pre) v = fmaxf(v, 0.f);
            }
            ins2[(y * 18 + x) * 8 + (ci & 3) * 2 + (ci >> 2)] = f2tff(v);
        }
        // stage weights: 9 taps x 8 ci x 64 co, paired-k layout
        for (int idx = tid; idx < 4608; idx += 256) {
            int co = idx & 63, t = idx >> 6;      // t = tap*8+ci
            int ci = t & 7, tap = t >> 3;
            wsm2[(tap * 4 + (ci & 3)) * WST + 2 * co + (ci >> 2)] =
                wT[(tap * cin + cc + ci) * 64 + co];
        }
        __syncthreads();

#pragma unroll
        for (int tap = 0; tap < 9; ++tap) {
            const int ky = tap / 3, kx = tap - 3 * (tap / 3);
            unsigned b[4][2];
            {
                const float* wr = wsm2 + (tap * 4 + tc) * WST;
#pragma unroll
                for (int j = 0; j < 4; ++j) {
                    int n = nw * 32 + j * 8 + gid;
                    float2 bv = *reinterpret_cast<const float2*>(wr + 2 * n);
                    b[j][0] = __float_as_uint(bv.x);
                    b[j][1] = __float_as_uint(bv.y);
                }
            }
#pragma unroll
            for (int i = 0; i < 4; ++i) {
                const int pixbase = (4 * mw + i + ky) * 18 + kx;
                float2 a0 = *reinterpret_cast<const float2*>(ins2 + (pixbase + gid) * 8 + 2 * tc);
                float2 a1 = *reinterpret_cast<const float2*>(ins2 + (pixbase + gid + 8) * 8 + 2 * tc);
                unsigned a[4];
                a[0] = __float_as_uint(a0.x);
                a[1] = __float_as_uint(a1.x);
                a[2] = __float_as_uint(a0.y);
                a[3] = __float_as_uint(a1.y);
#pragma unroll
                for (int j = 0; j < 4; ++j) mma_tf32(c[i][j], a, b[j]);
            }
        }
        __syncthreads();
    }

    // epilogue: bias + store + (optional) per-channel sum/sumsq
#pragma unroll
    for (int j = 0; j < 4; ++j) {
        const int co = nw * 32 + j * 8 + 2 * tc;
        const float b0 = bias[co], b1 = bias[co + 1];
        float s0 = 0.f, q0 = 0.f, s1 = 0.f, q1 = 0.f;
#pragma unroll
        for (int i = 0; i < 4; ++i) {
            const int gy = by * 16 + 4 * mw + i;
            const int gx = bx * 16;
            float v0 = c[i][j][0] + b0;
            float v1 = c[i][j][1] + b1;
            float v2 = c[i][j][2] + b0;
            float v3 = c[i][j][3] + b1;
            out[co * UV2 + gy * 256 + gx + gid]           = v0;
            out[(co + 1) * UV2 + gy * 256 + gx + gid]     = v1;
            out[co * UV2 + gy * 256 + gx + gid + 8]       = v2;
            out[(co + 1) * UV2 + gy * 256 + gx + gid + 8] = v3;
            s0 += v0 + v2; q0 += v0 * v0 + v2 * v2;
            s1 += v1 + v3; q1 += v1 * v1 + v3 * v3;
        }
        if (do_stats) {
#pragma unroll
            for (int off = 4; off < 32; off <<= 1) {
                s0 += __shfl_xor_sync(0xffffffffu, s0, off);
                q0 += __shfl_xor_sync(0xffffffffu, q0, off);
                s1 += __shfl_xor_sync(0xffffffffu, s1, off);
                q1 += __shfl_xor_sync(0xffffffffu, q1, off);
            }
            if (gid == 0) {
                atomicAdd(&g_ssum[co], s0);
                atomicAdd(&g_ssum[64 + co], q0);
                atomicAdd(&g_ssum[co + 1], s1);
                atomicAdd(&g_ssum[64 + co + 1], q1);
            }
        }
    }
}

// finalize instance-norm stats, reset accumulators
__global__ void finalize_stats_kernel() {
    int c = threadIdx.x;
    float s = g_ssum[c], q = g_ssum[64 + c];
    float m = s * (1.f / UV2);
    float var = q * (1.f / UV2) - m * m;
    g_stats[c] = m;
    g_stats[64 + c] = rsqrtf(fmaxf(var, 0.f) + 1e-5f);
    g_ssum[c] = 0.f;
    g_ssum[64 + c] = 0.f;
}

// conv_out (tensor): 64 -> 3 (padded 8), input IN'd, sigmoid.
// 16x16 tile, 8 warps x 2 rows; warp = 2 m16 x 1 n8.
__global__ void __launch_bounds__(256) convout_tf32_kernel(
    const float* __restrict__ in,
    const float* __restrict__ bias,
    float* __restrict__ out) {
    __shared__ __align__(16) float ins2[18 * 18 * 8];
    __shared__ __align__(16) float wsmo[9 * 4 * 40];

    const int tid  = threadIdx.x;
    const int lane = tid & 31, warp = tid >> 5;
    const int gid = lane >> 2, tc = lane & 3;
    const int bx = blockIdx.x, by = blockIdx.y;

    float c[2][4] = {};

    for (int cc = 0; cc < CC; cc += 8) {
        for (int idx = tid; idx < 2592; idx += 256) {
            int ci = idx / 324, rem = idx - ci * 324;
            int y = rem / 18, x = rem - y * 18;
            int gy = by * 16 + y - 1, gx = bx * 16 + x - 1;
            float v = 0.f;
            if ((unsigned)gy < 256u && (unsigned)gx < 256u) {
                v = in[(cc + ci) * UV2 + gy * 256 + gx];
                v = (v - g_stats[cc + ci]) * g_stats[64 + cc + ci];
            }
            ins2[(y * 18 + x) * 8 + (ci & 3) * 2 + (ci >> 2)] = f2tff(v);
        }
        for (int idx = tid; idx < 576; idx += 256) {
            int co = idx & 7, t = idx >> 3;     // t = tap*8+ci
            int ci = t & 7, tap = t >> 3;
            wsmo[(tap * 4 + (ci & 3)) * 40 + 2 * co + (ci >> 2)] =
                g_wTo[(tap * 64 + cc + ci) * 8 + co];
        }
        __syncthreads();

#pragma unroll
        for (int tap = 0; tap < 9; ++tap) {
            const int ky = tap / 3, kx = tap - 3 * (tap / 3);
            float2 bv = *reinterpret_cast<const float2*>(wsmo + (tap * 4 + tc) * 40 + 2 * gid);
            unsigned b[2] = {__float_as_uint(bv.x), __float_as_uint(bv.y)};
#pragma unroll
            for (int i = 0; i < 2; ++i) {
                const int pixbase = (2 * warp + i + ky) * 18 + kx;
                float2 a0 = *reinterpret_cast<const float2*>(ins2 + (pixbase + gid) * 8 + 2 * tc);
                float2 a1 = *reinterpret_cast<const float2*>(ins2 + (pixbase + gid + 8) * 8 + 2 * tc);
                unsigned a[4];
                a[0] = __float_as_uint(a0.x);
                a[1] = __float_as_uint(a1.x);
                a[2] = __float_as_uint(a0.y);
                a[3] = __float_as_uint(a1.y);
                mma_tf32(c[i], a, b);
            }
        }
        __syncthreads();
    }

    // epilogue: bias + sigmoid, store couts 0..2 only
#pragma unroll
    for (int i = 0; i < 2; ++i) {
        const int gy = by * 16 + 2 * warp + i;
        const int gx = bx * 16;
        const int co = 2 * tc;
        if (co < 3) {
            float v0 = 1.f / (1.f + expf(-(c[i][0] + bias[co])));
            float v2 = 1.f / (1.f + expf(-(c[i][2] + bias[co])));
            out[co * UV2 + gy * 256 + gx + gid]     = v0;
            out[co * UV2 + gy * 256 + gx + gid + 8] = v2;
        }
        if (co + 1 < 3) {
            float v1 = 1.f / (1.f + expf(-(c[i][1] + bias[co + 1])));
            float v3 = 1.f / (1.f + expf(-(c[i][3] + bias[co + 1])));
            out[(co + 1) * UV2 + gy * 256 + gx + gid]     = v1;
            out[(co + 1) * UV2 + gy * 256 + gx + gid + 8] = v3;
        }
    }
    // reset part counters for next graph replay (last kernel in the graph)
    if (bx == 0 && by == 0 && tid < P_N) g_cnt[tid] = 0;
}

// ============================================================
// host launch
// ============================================================
#define MLP_SMEM ((48 * AST + 2 * 128 * AST + 32 * WST) * 4 + 128 * 4 + 256)

extern "C" void kernel_launch(void* const* d_in, const int* in_sizes, int n_in,
                              void* d_out, int out_size) {
    const float* latent_z = (const float*)d_in[0];
    const float* latent_f = (const float*)d_in[1];
    const float* cano_xyz = (const float*)d_in[2];
    const float* w1in  = (const float*)d_in[3];
    const float* b1in  = (const float*)d_in[4];
    const float* w1hid = (const float*)d_in[5];
    const float* b1hid = (const float*)d_in[6];
    const float* w1out = (const float*)d_in[7];
    const float* b1out = (const float*)d_in[8];
    const float* w2in  = (const float*)d_in[9];
    const float* b2in  = (const float*)d_in[10];
    const float* w2hid = (const float*)d_in[11];
    const float* b2hid = (const float*)d_in[12];
    const float* w2out = (const float*)d_in[13];
    const float* b2out = (const float*)d_in[14];
    const float* cinw  = (const float*)d_in[15];
    const float* cinb  = (const float*)d_in[16];
    const float* chw   = (const float*)d_in[17];
    const float* chb   = (const float*)d_in[18];
    const float* cow   = (const float*)d_in[19];
    const float* cobb  = (const float*)d_in[20];
    const int* gs_part = (const int*)d_in[21];
    const int* uv_idx  = (const int*)d_in[22];
    float* out = (float*)d_out;

    cudaFuncSetAttribute(mlp_kernel, cudaFuncAttributeMaxDynamicSharedMemorySize, MLP_SMEM);

    float *uvmap, *buf0, *buf1, *wT;
    cudaGetSymbolAddress((void**)&uvmap, g_uvmap);
    cudaGetSymbolAddress((void**)&buf0, g_buf0);
    cudaGetSymbolAddress((void**)&buf1, g_buf1);
    cudaGetSymbolAddress((void**)&wT, g_wT);

    clearcount_kernel<<<2048, 256>>>(gs_part);                       // 1
    partbias_offsets_kernel<<<6, 128>>>(latent_f, w1in, b1in, w2in, b2in); // 2
    scatter_kernel<<<(G_N + 255) / 256, 256>>>(gs_part);             // 3
    mlp_kernel<<<G_N / 64 + P_N, 256, MLP_SMEM>>>(latent_z, cano_xyz,  // 4 (capture)
        w1in, w1hid, b1hid, w1out, b1out,
        w2in, w2hid, b2hid, w2out, b2out, uv_idx);

    transpose_w_kernel<<<(WT_IN_SZ + 3 * WT_HID_SZ + WT_OUT_SZ + 255) / 256, 256>>>(cinw, chw, cow);

    dim3 cgrid(UVN / 16, UVN / 16);
    conv3x3_tf32_kernel<<<cgrid, 256>>>(uvmap, HD, wT, cinb, buf0, 0, 0);
    conv3x3_tf32_kernel<<<cgrid, 256>>>(buf0, CC, wT + WT_IN_SZ, chb, buf1, 1, 1);
    finalize_stats_kernel<<<1, 64>>>();
    conv3x3_tf32_kernel<<<cgrid, 256>>>(buf1, CC, wT + WT_IN_SZ + WT_HID_SZ, chb + CC, buf0, 2, 1);
    finalize_stats_kernel<<<1, 64>>>();
    conv3x3_tf32_kernel<<<cgrid, 256>>>(buf0, CC, wT + WT_IN_SZ + 2 * WT_HID_SZ, chb + 2 * CC, buf1, 2, 1);
    finalize_stats_kernel<<<1, 64>>>();
    convout_tf32_kernel<<<cgrid, 256>>>(buf1, cobb, out);
}